// round 12
// baseline (speedup 1.0000x reference)
#include <cuda_runtime.h>
#include <cuda_fp16.h>
#include <cstdint>

// ----------------------------------------------------------------------------
// BitLinear: y = RMSNorm(x) @ w_q^T * gamma
// R1: harness PTX is baseline sm_103 (no 'a') -> no tcgen05.
// R9 (BEST 553us): fp16 HMMA, 64x64 warp tiles, occ2, tensor 89.5%; HMMA floor.
// R10/R11 persistence FAILED (addressing ALU / regs).
// R12: int8 two-plane IMMA m16n8k32 (4096 MAC/instr, 2x HMMA):
//      xn ~= s1*q1 + (s1/128)*q2 (15-bit eff. quant, rel_err ~1e-4, exact i32
//      accum). Both planes share B frags. s8-k32 frags are byte-identical to
//      f16-k16 frags -> proven swizzle/ldmatrix addressing unchanged.
//      CTA 128x64, warp 64x32, acc 2x64 int32; 2 stages x 40KB; occ 2.
// ----------------------------------------------------------------------------

#define DIN   4096
#define DOUT  4096
#define MROWS 8192

__device__ __align__(256) int8_t g_q1[(size_t)MROWS * DIN];
__device__ __align__(256) int8_t g_q2[(size_t)MROWS * DIN];
__device__ __align__(256) int8_t g_w8[(size_t)DOUT * DIN];
__device__ float g_s1[MROWS];

// ---------------------------- PTX helpers -----------------------------------
__device__ __forceinline__ uint32_t smem_u32(const void* p) {
    uint32_t a;
    asm("{ .reg .u64 t; cvta.to.shared.u64 t, %1; cvt.u32.u64 %0, t; }"
        : "=r"(a) : "l"(p));
    return a;
}

__device__ __forceinline__ void cp_async16(uint32_t dst, const void* src) {
    asm volatile("cp.async.cg.shared.global [%0], [%1], 16;"
                 :: "r"(dst), "l"(src));
}

#define CP_COMMIT() asm volatile("cp.async.commit_group;" ::: "memory")

#define LDSM_X4(r0, r1, r2, r3, addr) \
    asm volatile("ldmatrix.sync.aligned.m8n8.x4.shared.b16 {%0,%1,%2,%3}, [%4];" \
                 : "=r"(r0), "=r"(r1), "=r"(r2), "=r"(r3) : "r"(addr))

#define IMMA16832(d, a, b0, b1) \
    asm volatile("mma.sync.aligned.m16n8k32.row.col.s32.s8.s8.s32 " \
                 "{%0,%1,%2,%3}, {%4,%5,%6,%7}, {%8,%9}, {%0,%1,%2,%3};" \
                 : "+r"((d)[0]), "+r"((d)[1]), "+r"((d)[2]), "+r"((d)[3]) \
                 : "r"((a)[0]), "r"((a)[1]), "r"((a)[2]), "r"((a)[3]), \
                   "r"(b0), "r"(b1))

// ----------------------------- GEMM config ----------------------------------
constexpr int BM = 128, BN = 64, BK = 128;     // BK in int8 elems = 128 B rows
constexpr int KTILES = DIN / BK;               // 32
constexpr int A_TILE = BM * BK;                // 16384 B per plane
constexpr int B_TILE = BN * BK;                // 8192 B
constexpr int STAGE_B = 2 * A_TILE + B_TILE;   // 40960
constexpr int STAGES = 2;
constexpr int SMEM_SZ = STAGES * STAGE_B;      // 81920 (2 CTAs/SM fit)
constexpr int NTHREADS = 128;                  // 4 warps, warp tile 64x32

// ------------------------ Kernel 0: dummy (ncu window shift) -----------------
__global__ void dummy_kernel() {}

// ------------------ Kernel 1: RMSNorm -> two-plane int8 ----------------------
__global__ __launch_bounds__(256) void rmsnorm_q_kernel(
    const float* __restrict__ x, const float* __restrict__ nw) {
    const int row = blockIdx.x;
    const float4* xr = reinterpret_cast<const float4*>(x) + (size_t)row * (DIN / 4);
    const float4* nw4 = reinterpret_cast<const float4*>(nw);
    const int t = threadIdx.x;

    float4 v[4], w[4];
    float ss = 0.f;
#pragma unroll
    for (int i = 0; i < 4; i++) {
        v[i] = xr[t + i * 256];
        w[i] = nw4[t + i * 256];
        ss += v[i].x * v[i].x + v[i].y * v[i].y + v[i].z * v[i].z + v[i].w * v[i].w;
    }
#pragma unroll
    for (int o = 16; o > 0; o >>= 1) ss += __shfl_xor_sync(0xffffffffu, ss, o);

    __shared__ float wss[8], wmx[8];
    __shared__ float s_scale, s_inv1;
    if ((t & 31) == 0) wss[t >> 5] = ss;
    __syncthreads();
    if (t == 0) {
        float tot = 0.f;
#pragma unroll
        for (int i = 0; i < 8; i++) tot += wss[i];
        s_scale = rsqrtf(tot * (1.0f / DIN) + 1e-6f);
    }
    __syncthreads();
    const float sc = s_scale;

    // normalized values + row max
    float xn[16];
    float amax = 0.f;
#pragma unroll
    for (int i = 0; i < 4; i++) {
        xn[4 * i + 0] = v[i].x * sc * w[i].x;
        xn[4 * i + 1] = v[i].y * sc * w[i].y;
        xn[4 * i + 2] = v[i].z * sc * w[i].z;
        xn[4 * i + 3] = v[i].w * sc * w[i].w;
#pragma unroll
        for (int j = 0; j < 4; j++) amax = fmaxf(amax, fabsf(xn[4 * i + j]));
    }
#pragma unroll
    for (int o = 16; o > 0; o >>= 1)
        amax = fmaxf(amax, __shfl_xor_sync(0xffffffffu, amax, o));
    if ((t & 31) == 0) wmx[t >> 5] = amax;
    __syncthreads();
    if (t == 0) {
        float m = 1e-8f;
#pragma unroll
        for (int i = 0; i < 8; i++) m = fmaxf(m, wmx[i]);
        g_s1[row] = m * (1.0f / 127.0f);
        s_inv1 = 127.0f / m;
    }
    __syncthreads();
    const float inv1 = s_inv1;
    const float s1 = 1.0f / inv1;
    const float inv2 = 128.0f * inv1;

    uint32_t* o1 = reinterpret_cast<uint32_t*>(g_q1 + (size_t)row * DIN);
    uint32_t* o2 = reinterpret_cast<uint32_t*>(g_q2 + (size_t)row * DIN);
#pragma unroll
    for (int i = 0; i < 4; i++) {
        uint32_t p1 = 0, p2 = 0;
#pragma unroll
        for (int j = 0; j < 4; j++) {
            const float xv = xn[4 * i + j];
            const int q1 = __float2int_rn(xv * inv1);
            const float r = xv - (float)q1 * s1;
            const int q2 = __float2int_rn(r * inv2);
            p1 |= (uint32_t)((uint8_t)(int8_t)q1) << (8 * j);
            p2 |= (uint32_t)((uint8_t)(int8_t)q2) << (8 * j);
        }
        o1[t + i * 256] = p1;
        o2[t + i * 256] = p2;
    }
}

// ------------------------ Kernel 2: w_q fp32 -> int8 -------------------------
__global__ __launch_bounds__(256) void wconv8_kernel(const float* __restrict__ w) {
    const size_t gid = (size_t)blockIdx.x * 256 + threadIdx.x;
    const float4* w4 = reinterpret_cast<const float4*>(w);
    uint32_t* o = reinterpret_cast<uint32_t*>(g_w8);
#pragma unroll
    for (int i = 0; i < 4; i++) {
        size_t idx = gid + (size_t)i * 1048576;   // float4 index == char4 index
        float4 v = w4[idx];
        uint32_t p = 0;
        p |= (uint32_t)((uint8_t)(int8_t)__float2int_rn(v.x));
        p |= (uint32_t)((uint8_t)(int8_t)__float2int_rn(v.y)) << 8;
        p |= (uint32_t)((uint8_t)(int8_t)__float2int_rn(v.z)) << 16;
        p |= (uint32_t)((uint8_t)(int8_t)__float2int_rn(v.w)) << 24;
        o[idx] = p;
    }
}

// ------------------------ Kernel 3: IMMA GEMM --------------------------------
// 128 threads = 4 warps, 2(m) x 2(n), warp tile 64x32; 2 CTAs/SM; 2 stages.
// Per kk (k32): 10 ldmatrix.x4 (A1 4, A2 4, B 2) + 32 IMMA (planes share B).
__global__ __launch_bounds__(NTHREADS, 2)
void bitlinear_gemm_kernel(const float* __restrict__ gamma, float* __restrict__ out) {
    extern __shared__ char smem[];
    const uint32_t sb = smem_u32(smem);
    const int tid = threadIdx.x;
    const int wid = tid >> 5;
    const int lane = tid & 31;
    const int warp_m = wid >> 1;       // 0..1
    const int warp_n = wid & 1;        // 0..1
    const int m0 = blockIdx.y * BM;
    const int n0 = blockIdx.x * BN;

    // ---- copy geometry: 16B chunks; 128B rows; XOR swizzle (same as fp16)
    const int cc = tid & 7;
    const int r0c = tid >> 3;          // 0..15; r&7 invariant under +16
    const uint32_t so_base = (uint32_t)(r0c * 128 + ((cc ^ (r0c & 7)) << 4));
    const char* gA1 = (const char*)g_q1 + (size_t)(m0 + r0c) * DIN + cc * 16;
    const char* gA2 = (const char*)g_q2 + (size_t)(m0 + r0c) * DIN + cc * 16;
    const char* gB  = (const char*)g_w8 + (size_t)(n0 + r0c) * DIN + cc * 16;

    auto fill = [&](int kt, int slot) {
        const uint32_t sdst = sb + (uint32_t)slot * STAGE_B + so_base;
        const uint32_t koff = (uint32_t)kt * 128;
#pragma unroll
        for (int i = 0; i < 8; i++)   // A1: 128 rows
            cp_async16(sdst + i * (16 * 128),
                       gA1 + koff + (size_t)i * (16 * DIN));
#pragma unroll
        for (int i = 0; i < 8; i++)   // A2
            cp_async16(sdst + A_TILE + i * (16 * 128),
                       gA2 + koff + (size_t)i * (16 * DIN));
#pragma unroll
        for (int i = 0; i < 4; i++)   // B: 64 rows
            cp_async16(sdst + 2 * A_TILE + i * (16 * 128),
                       gB + koff + (size_t)i * (16 * DIN));
    };

    // ---- ldmatrix base offsets (kk=0); off(kk) = off0 ^ (kk << 5)
    const int rA0 = warp_m * 64 + (lane & 15);
    const int cgA = lane >> 4;
    const int gB4 = lane >> 3;
    const int rB0 = warp_n * 32 + ((gB4 & 2) << 2) + (lane & 7);
    const int cgB = gB4 & 1;

    uint32_t offA0[4], offB0[2];
#pragma unroll
    for (int mi = 0; mi < 4; mi++) {
        const int r = rA0 + mi * 16;
        offA0[mi] = (uint32_t)(r * 128 + ((cgA ^ (r & 7)) << 4));
    }
#pragma unroll
    for (int p = 0; p < 2; p++) {
        const int r = rB0 + p * 16;
        offB0[p] = (uint32_t)(r * 128 + ((cgB ^ (r & 7)) << 4)) + 2 * A_TILE;
    }

    int acc1[4][4][4], acc2[4][4][4];
#pragma unroll
    for (int mi = 0; mi < 4; mi++)
#pragma unroll
        for (int nf = 0; nf < 4; nf++)
#pragma unroll
            for (int e = 0; e < 4; e++) { acc1[mi][nf][e] = 0; acc2[mi][nf][e] = 0; }

    uint32_t a1f[2][4][4], a2f[2][4][4], bqf[2][2][4];

    auto load_frags = [&](int buf, uint32_t base, int kk) {
        const uint32_t kx = (uint32_t)(kk << 5);
#pragma unroll
        for (int mi = 0; mi < 4; mi++)
            LDSM_X4(a1f[buf][mi][0], a1f[buf][mi][1], a1f[buf][mi][2],
                    a1f[buf][mi][3], base + (offA0[mi] ^ kx));
#pragma unroll
        for (int mi = 0; mi < 4; mi++)
            LDSM_X4(a2f[buf][mi][0], a2f[buf][mi][1], a2f[buf][mi][2],
                    a2f[buf][mi][3], base + A_TILE + (offA0[mi] ^ kx));
#pragma unroll
        for (int p = 0; p < 2; p++)
            LDSM_X4(bqf[buf][p][0], bqf[buf][p][1], bqf[buf][p][2],
                    bqf[buf][p][3], base + (offB0[p] ^ kx));
    };

    auto do_mma = [&](int buf) {
#pragma unroll
        for (int mi = 0; mi < 4; mi++)
#pragma unroll
            for (int p = 0; p < 2; p++)
#pragma unroll
                for (int h = 0; h < 2; h++) {
                    const int nf = p * 2 + h;
                    IMMA16832(acc1[mi][nf], a1f[buf][mi],
                              bqf[buf][p][2 * h], bqf[buf][p][2 * h + 1]);
                    IMMA16832(acc2[mi][nf], a2f[buf][mi],
                              bqf[buf][p][2 * h], bqf[buf][p][2 * h + 1]);
                }
    };

    // ---- prologue: stage 0, wait, publish, prefetch kk0 frags
    fill(0, 0); CP_COMMIT();
    asm volatile("cp.async.wait_group 0;" ::: "memory");
    __syncthreads();
    load_frags(0, sb, 0);

    // ---- main loop (2-stage double buffer; frags one kk ahead)
    for (int kt = 0; kt < KTILES; kt++) {
        const uint32_t base = sb + (uint32_t)(kt & 1) * STAGE_B;

        if (kt + 1 < KTILES) { fill(kt + 1, (kt + 1) & 1); CP_COMMIT(); }

#pragma unroll
        for (int kk = 0; kk < 3; kk++) {
            load_frags((kk + 1) & 1, base, kk + 1);
            do_mma(kk & 1);
        }
        do_mma(1);   // kk=3

        asm volatile("cp.async.wait_group 0;" ::: "memory");
        __syncthreads();

        if (kt + 1 < KTILES)
            load_frags(0, sb + (uint32_t)((kt + 1) & 1) * STAGE_B, 0);
    }

    // ---- epilogue: y = gamma[n] * (s1[m]*A1 + (s1[m]/128)*A2)
    const int col_l = (lane & 3) * 2;
    const float* gptr = gamma + n0 + warp_n * 32;
    float gv0[4], gv1[4];
#pragma unroll
    for (int nf = 0; nf < 4; nf++) {
        gv0[nf] = __ldg(gptr + nf * 8 + col_l);
        gv1[nf] = __ldg(gptr + nf * 8 + col_l + 1);
    }

    const int row_base = m0 + warp_m * 64 + (lane >> 2);
#pragma unroll
    for (int mi = 0; mi < 4; mi++) {
        const int r = row_base + mi * 16;
        const float s1a = __ldg(g_s1 + r);
        const float s1b = __ldg(g_s1 + r + 8);
        const float s2a = s1a * 0.0078125f;
        const float s2b = s1b * 0.0078125f;
        float* op0 = out + (size_t)r * DOUT + n0 + warp_n * 32;
        float* op1 = op0 + (size_t)8 * DOUT;
#pragma unroll
        for (int nf = 0; nf < 4; nf++) {
            float2 v0, v1;
            v0.x = gv0[nf] * ((float)acc1[mi][nf][0] * s1a + (float)acc2[mi][nf][0] * s2a);
            v0.y = gv1[nf] * ((float)acc1[mi][nf][1] * s1a + (float)acc2[mi][nf][1] * s2a);
            v1.x = gv0[nf] * ((float)acc1[mi][nf][2] * s1b + (float)acc2[mi][nf][2] * s2b);
            v1.y = gv1[nf] * ((float)acc1[mi][nf][3] * s1b + (float)acc2[mi][nf][3] * s2b);
            *reinterpret_cast<float2*>(op0 + nf * 8 + col_l) = v0;
            *reinterpret_cast<float2*>(op1 + nf * 8 + col_l) = v1;
        }
    }
}

// ------------------------------- launch --------------------------------------
extern "C" void kernel_launch(void* const* d_in, const int* in_sizes, int n_in,
                              void* d_out, int out_size) {
    const float* x     = (const float*)d_in[0];  // [2,4096,4096]
    const float* nw    = (const float*)d_in[1];  // [4096]
    const float* wq    = (const float*)d_in[2];  // [4096,4096]
    const float* gamma = (const float*)d_in[3];  // [4096]
    float* out = (float*)d_out;

    cudaFuncSetAttribute(bitlinear_gemm_kernel,
                         cudaFuncAttributeMaxDynamicSharedMemorySize, SMEM_SZ);

    dummy_kernel<<<1, 32>>>();   // keeps ncu -s5 capture on the GEMM
    rmsnorm_q_kernel<<<MROWS, 256>>>(x, nw);
    wconv8_kernel<<<4096, 256>>>(wq);
    bitlinear_gemm_kernel<<<dim3(DOUT / BN, MROWS / BM), NTHREADS, SMEM_SZ>>>(gamma, out);
}

// round 13
// speedup vs baseline: 6.4988x; 6.4988x over previous
#include <cuda_runtime.h>
#include <cuda_fp16.h>
#include <cstdint>

// ----------------------------------------------------------------------------
// BitLinear: y = RMSNorm(x) @ w_q^T * gamma
// R1: harness PTX is baseline sm_103 (no 'a') -> no tcgen05.
// R9 (BEST 553us): fp16 HMMA, 64x64 warp tiles, 128-thr CTAs, occ2,
//     tensor 89.5%, GEMM 508us (~7% off legacy-HMMA floor).
// R10/R11 persistence FAILED. R12 int8 IMMA FAILED (legacy s8 mma.sync is
//     ~50+ cyc/SMSP on sm_103 -- deprecated pipe; 3568us).
// R13: R9 GEMM verbatim + prepasses (rmsnorm, wconv) merged into ONE launch
//     partitioned by blockIdx (overlapping their DRAM streams).
// ----------------------------------------------------------------------------

#define DIN   4096
#define DOUT  4096
#define MROWS 8192

__device__ __align__(256) __half g_xn[(size_t)MROWS * DIN];
__device__ __align__(256) __half g_wq[(size_t)DOUT * DIN];

// ---------------------------- PTX helpers -----------------------------------
__device__ __forceinline__ uint32_t smem_u32(const void* p) {
    uint32_t a;
    asm("{ .reg .u64 t; cvta.to.shared.u64 t, %1; cvt.u32.u64 %0, t; }"
        : "=r"(a) : "l"(p));
    return a;
}

__device__ __forceinline__ void cp_async16(uint32_t dst, const void* src) {
    asm volatile("cp.async.cg.shared.global [%0], [%1], 16;"
                 :: "r"(dst), "l"(src));
}

#define CP_COMMIT() asm volatile("cp.async.commit_group;" ::: "memory")

#define LDSM_X4(r0, r1, r2, r3, addr) \
    asm volatile("ldmatrix.sync.aligned.m8n8.x4.shared.b16 {%0,%1,%2,%3}, [%4];" \
                 : "=r"(r0), "=r"(r1), "=r"(r2), "=r"(r3) : "r"(addr))

#define MMA16816(d, a, b0, b1) \
    asm volatile("mma.sync.aligned.m16n8k16.row.col.f32.f16.f16.f32 " \
                 "{%0,%1,%2,%3}, {%4,%5,%6,%7}, {%8,%9}, {%0,%1,%2,%3};" \
                 : "+f"((d)[0]), "+f"((d)[1]), "+f"((d)[2]), "+f"((d)[3]) \
                 : "r"((a)[0]), "r"((a)[1]), "r"((a)[2]), "r"((a)[3]), \
                   "r"(b0), "r"(b1))

// ----------------------------- GEMM config ----------------------------------
constexpr int BM = 128, BN = 128, BK = 64;
constexpr int KTILES = DIN / BK;               // 64
constexpr int STAGES = 3;
constexpr int TILE_B  = BM * BK * 2;           // 16384 B per fp16 tile
constexpr int STAGE_B = 2 * TILE_B;            // A + B = 32768
constexpr int SMEM_SZ = STAGES * STAGE_B;      // 98304 (2 CTAs/SM)
constexpr int NTHREADS = 128;                  // 4 warps, warp tile 64x64

// --------------- Kernel 1: merged prepass (rmsnorm + wconv) ------------------
// blocks [0, MROWS): RMSNorm row -> fp16 xn
// blocks [MROWS, MROWS+4096): w_q fp32 -> fp16 (4096 elems per block)
__global__ __launch_bounds__(256) void prepass_kernel(
    const float* __restrict__ x, const float* __restrict__ nw,
    const float* __restrict__ wq) {
    const int b = blockIdx.x;
    const int t = threadIdx.x;

    if (b < MROWS) {
        // ---------------- RMSNorm -> fp16 ----------------
        const int row = b;
        const float4* xr = reinterpret_cast<const float4*>(x) + (size_t)row * (DIN / 4);
        const float4* nw4 = reinterpret_cast<const float4*>(nw);

        float4 v[4];
        float ss = 0.f;
#pragma unroll
        for (int i = 0; i < 4; i++) {
            v[i] = xr[t + i * 256];
            ss += v[i].x * v[i].x + v[i].y * v[i].y + v[i].z * v[i].z + v[i].w * v[i].w;
        }
#pragma unroll
        for (int o = 16; o > 0; o >>= 1) ss += __shfl_xor_sync(0xffffffffu, ss, o);

        __shared__ float wss[8];
        __shared__ float s_scale;
        if ((t & 31) == 0) wss[t >> 5] = ss;
        __syncthreads();
        if (t == 0) {
            float tot = 0.f;
#pragma unroll
            for (int i = 0; i < 8; i++) tot += wss[i];
            s_scale = rsqrtf(tot * (1.0f / DIN) + 1e-6f);
        }
        __syncthreads();
        const float sc = s_scale;

        uint2* xo = reinterpret_cast<uint2*>(g_xn + (size_t)row * DIN);
#pragma unroll
        for (int i = 0; i < 4; i++) {
            float4 w = nw4[t + i * 256];
            __half2 h01 = __floats2half2_rn(v[i].x * sc * w.x, v[i].y * sc * w.y);
            __half2 h23 = __floats2half2_rn(v[i].z * sc * w.z, v[i].w * sc * w.w);
            uint2 u;
            u.x = *reinterpret_cast<uint32_t*>(&h01);
            u.y = *reinterpret_cast<uint32_t*>(&h23);
            xo[t + i * 256] = u;
        }
    } else {
        // ---------------- w_q fp32 -> fp16 ----------------
        const size_t gid = (size_t)(b - MROWS) * 256 + t;     // 1,048,576 total
        const float4* w4 = reinterpret_cast<const float4*>(wq);
        uint2* o = reinterpret_cast<uint2*>(g_wq);
#pragma unroll
        for (int i = 0; i < 4; i++) {
            size_t idx = gid + (size_t)i * 1048576;
            float4 v = w4[idx];
            __half2 h01 = __floats2half2_rn(v.x, v.y);
            __half2 h23 = __floats2half2_rn(v.z, v.w);
            uint2 u;
            u.x = *reinterpret_cast<uint32_t*>(&h01);
            u.y = *reinterpret_cast<uint32_t*>(&h23);
            o[idx] = u;
        }
    }
}

// ------------------------ Kernel 2: HMMA GEMM (R9) ---------------------------
// 128 threads = 4 warps, 2(m) x 2(n), warp tile 64x64; 2 CTAs/SM.
// All fragments one kk-step ahead; barrier after kk3 HMMAs.
__global__ __launch_bounds__(NTHREADS, 2)
void bitlinear_gemm_kernel(const float* __restrict__ gamma, float* __restrict__ out) {
    extern __shared__ char smem[];
    const uint32_t sb = smem_u32(smem);
    const int tid = threadIdx.x;
    const int wid = tid >> 5;
    const int lane = tid & 31;
    const int warp_m = wid >> 1;       // 0..1
    const int warp_n = wid & 1;        // 0..1
    const int m0 = blockIdx.y * BM;
    const int n0 = blockIdx.x * BN;

    // ---- per-thread copy geometry: 1024 chunks/tile, 128 thr -> 8 each
    const int cc = tid & 7;
    const int r0c = tid >> 3;          // 0..15; r&7 invariant under +16
    const uint32_t so_base = (uint32_t)(r0c * 128 + ((cc ^ (r0c & 7)) << 4));
    const char* gA = (const char*)g_xn + (size_t)(m0 + r0c) * (DIN * 2) + cc * 16;
    const char* gB = (const char*)g_wq + (size_t)(n0 + r0c) * (DIN * 2) + cc * 16;

    auto issue_stage = [&](int s, int kt) {
        const uint32_t sdst = sb + (uint32_t)s * STAGE_B + so_base;
        const uint32_t koff = (uint32_t)kt * 128;
#pragma unroll
        for (int i = 0; i < 8; i++)
            cp_async16(sdst + i * (16 * 128),
                       gA + koff + (size_t)i * (16 * DIN * 2));
#pragma unroll
        for (int i = 0; i < 8; i++)
            cp_async16(sdst + TILE_B + i * (16 * 128),
                       gB + koff + (size_t)i * (16 * DIN * 2));
    };

    // ---- ldmatrix base offsets (kk=0); off(kk) = off0 ^ (kk << 5)
    const int rA0 = warp_m * 64 + (lane & 15);
    const int cgA = lane >> 4;
    const int gB4 = lane >> 3;
    const int rB0 = warp_n * 64 + ((gB4 & 2) << 2) + (lane & 7);
    const int cgB = gB4 & 1;

    uint32_t offA0[4], offB0[4];
#pragma unroll
    for (int mi = 0; mi < 4; mi++) {
        const int r = rA0 + mi * 16;
        offA0[mi] = (uint32_t)(r * 128 + ((cgA ^ (r & 7)) << 4));
    }
#pragma unroll
    for (int p = 0; p < 4; p++) {
        const int r = rB0 + p * 16;
        offB0[p] = (uint32_t)(r * 128 + ((cgB ^ (r & 7)) << 4)) + TILE_B;
    }

    float acc[4][8][4];
#pragma unroll
    for (int mi = 0; mi < 4; mi++)
#pragma unroll
        for (int nj = 0; nj < 8; nj++)
#pragma unroll
            for (int e = 0; e < 4; e++) acc[mi][nj][e] = 0.f;

    uint32_t af[2][4][4], bf[2][4][4];   // [buf][frag][reg]

    auto load_frags = [&](int buf, uint32_t base, int kk) {
        const uint32_t kx = (uint32_t)(kk << 5);
#pragma unroll
        for (int mi = 0; mi < 4; mi++)
            LDSM_X4(af[buf][mi][0], af[buf][mi][1], af[buf][mi][2],
                    af[buf][mi][3], base + (offA0[mi] ^ kx));
#pragma unroll
        for (int p = 0; p < 4; p++)
            LDSM_X4(bf[buf][p][0], bf[buf][p][1], bf[buf][p][2],
                    bf[buf][p][3], base + (offB0[p] ^ kx));
    };

    auto do_mma = [&](int buf) {
#pragma unroll
        for (int mi = 0; mi < 4; mi++)
#pragma unroll
            for (int p = 0; p < 4; p++) {
                MMA16816(acc[mi][2 * p],     af[buf][mi], bf[buf][p][0], bf[buf][p][1]);
                MMA16816(acc[mi][2 * p + 1], af[buf][mi], bf[buf][p][2], bf[buf][p][3]);
            }
    };

    // ---- prologue: fill 2 stages, publish stage 0, prefetch its kk0 frags
    issue_stage(0, 0); CP_COMMIT();
    issue_stage(1, 1); CP_COMMIT();
    asm volatile("cp.async.wait_group 1;" ::: "memory");
    __syncthreads();
    load_frags(0, sb, 0);

    // ---- main loop: frags always one kk ahead; barrier after kk3 HMMAs
    int stage = 0;
    for (int kt = 0; kt < KTILES; kt++) {
        const uint32_t base = sb + (uint32_t)stage * STAGE_B;

        if (kt + 2 < KTILES) {
            int ns = stage + 2; if (ns >= STAGES) ns -= STAGES;
            issue_stage(ns, kt + 2);
        }
        CP_COMMIT();

#pragma unroll
        for (int kk = 0; kk < 3; kk++) {
            load_frags((kk + 1) & 1, base, kk + 1);
            do_mma(kk & 1);
        }
        do_mma(1);   // kk=3

        asm volatile("cp.async.wait_group 1;" ::: "memory");
        __syncthreads();

        int nstage = stage + 1; if (nstage >= STAGES) nstage -= STAGES;
        if (kt + 1 < KTILES)
            load_frags(0, sb + (uint32_t)nstage * STAGE_B, 0);
        stage = nstage;
    }

    // ---- epilogue: *gamma, write f32
    const int col_l = (lane & 3) * 2;
    const float* gptr = gamma + n0 + warp_n * 64;
    float gv0[8], gv1[8];
#pragma unroll
    for (int nj = 0; nj < 8; nj++) {
        gv0[nj] = __ldg(gptr + nj * 8 + col_l);
        gv1[nj] = __ldg(gptr + nj * 8 + col_l + 1);
    }

    const int row_base = m0 + warp_m * 64 + (lane >> 2);
#pragma unroll
    for (int mi = 0; mi < 4; mi++) {
        float* op0 = out + (size_t)(row_base + mi * 16) * DOUT + n0 + warp_n * 64;
        float* op1 = op0 + (size_t)8 * DOUT;
#pragma unroll
        for (int nj = 0; nj < 8; nj++) {
            float2 v0, v1;
            v0.x = acc[mi][nj][0] * gv0[nj];
            v0.y = acc[mi][nj][1] * gv1[nj];
            v1.x = acc[mi][nj][2] * gv0[nj];
            v1.y = acc[mi][nj][3] * gv1[nj];
            *reinterpret_cast<float2*>(op0 + nj * 8 + col_l) = v0;
            *reinterpret_cast<float2*>(op1 + nj * 8 + col_l) = v1;
        }
    }
}

// ------------------------------- launch --------------------------------------
extern "C" void kernel_launch(void* const* d_in, const int* in_sizes, int n_in,
                              void* d_out, int out_size) {
    const float* x     = (const float*)d_in[0];  // [2,4096,4096]
    const float* nw    = (const float*)d_in[1];  // [4096]
    const float* wq    = (const float*)d_in[2];  // [4096,4096]
    const float* gamma = (const float*)d_in[3];  // [4096]
    float* out = (float*)d_out;

    cudaFuncSetAttribute(bitlinear_gemm_kernel,
                         cudaFuncAttributeMaxDynamicSharedMemorySize, SMEM_SZ);

    prepass_kernel<<<MROWS + 4096, 256>>>(x, nw, wq);
    bitlinear_gemm_kernel<<<dim3(DOUT / BN, MROWS / BM), NTHREADS, SMEM_SZ>>>(gamma, out);
}